// round 2
// baseline (speedup 1.0000x reference)
#include <cuda_runtime.h>

#define N_NODES 50000
#define N_EDGES 800000
#define IN_F    64
#define OUT_F   32
#define N_STEPS 20
#define LR      0.1f
#define SLOPE   0.2f

// ---------------- scratch (device globals; no allocation allowed) ----------------
__device__ float    g_transformed[N_NODES * OUT_F];
__device__ float    g_agg[N_NODES * OUT_F];
__device__ float    g_mu[N_NODES * OUT_F];
__device__ float    g_deg[N_NODES];
__device__ float    g_es[N_NODES];
__device__ float    g_ed[N_NODES];
__device__ unsigned g_mmax[N_NODES];   // order-preserving encoded float max
__device__ float    g_ssum[N_NODES];
__device__ float    g_scores[N_EDGES];
__device__ float    g_evals[N_EDGES];

// Order-preserving float<->uint encoding for atomicMax on floats.
__device__ __forceinline__ unsigned f_enc(float x) {
    unsigned u = __float_as_uint(x);
    return (u & 0x80000000u) ? ~u : (u | 0x80000000u);
}
__device__ __forceinline__ float f_dec(unsigned k) {
    return (k & 0x80000000u) ? __uint_as_float(k & 0x7FFFFFFFu)
                             : __uint_as_float(~k);
}
// encoding of -inf: anything real encodes strictly above this
#define MMAX_INIT 0x007FFFFFu

// ---------------- kernels ----------------

__global__ void init_kernel() {
    int i = blockIdx.x * blockDim.x + threadIdx.x;
    if (i < N_NODES * OUT_F) {
        g_mu[i]  = 0.0f;
        g_agg[i] = 0.0f;
    }
    if (i < N_NODES) g_deg[i] = 0.0f;
}

// transformed = mu_upper @ W^T   (N x 64) @ (64 x 32)
__global__ void gemm_kernel(const float* __restrict__ mu_upper,
                            const float* __restrict__ W) {
    __shared__ float Ws[OUT_F * IN_F];
    for (int i = threadIdx.x; i < OUT_F * IN_F; i += blockDim.x)
        Ws[i] = W[i];
    __syncthreads();

    int tid = blockIdx.x * blockDim.x + threadIdx.x;
    if (tid >= N_NODES * OUT_F) return;
    int n = tid >> 5;          // node
    int f = tid & 31;          // out feature
    const float* row = mu_upper + n * IN_F;
    const float* w   = Ws + f * IN_F;
    float acc = 0.0f;
#pragma unroll
    for (int k = 0; k < IN_F; ++k)
        acc = fmaf(row[k], w[k], acc);
    g_transformed[tid] = acc;
}

__global__ void deg_kernel(const int* __restrict__ dst) {
    int e = blockIdx.x * blockDim.x + threadIdx.x;
    if (e >= N_EDGES) return;
    atomicAdd(&g_deg[dst[e]], 1.0f);
}

// first top-down: alpha0 = 1/(deg[dst]+1e-8); warp per edge, lane = feature
__global__ void topdown0_kernel(const int* __restrict__ src,
                                const int* __restrict__ dst) {
    int t = blockIdx.x * blockDim.x + threadIdx.x;
    int e = t >> 5;
    int lane = t & 31;
    if (e >= N_EDGES) return;
    int sN = src[e], dN = dst[e];
    float alpha = 1.0f / (g_deg[dN] + 1e-8f);
    float v = alpha * g_transformed[sN * OUT_F + lane];
    atomicAdd(&g_agg[dN * OUT_F + lane], v);
}

// per step: mu_hat=relu(agg); err=mu-mu_hat; es=err.a_src; ed=err.a_dst;
// mu -= LR*err;  reset agg / mmax / ssum for the upcoming softmax+aggregate.
__global__ void node_kernel(const float* __restrict__ a_vec) {
    int t = blockIdx.x * blockDim.x + threadIdx.x;
    int n = t >> 5;
    int lane = t & 31;
    if (n >= N_NODES) return;

    float aggv = g_agg[t];
    float mh = fmaxf(aggv, 0.0f);
    float mu = g_mu[t];
    float er = mu - mh;

    float ps = er * a_vec[lane];
    float pd = er * a_vec[OUT_F + lane];
#pragma unroll
    for (int off = 16; off > 0; off >>= 1) {
        ps += __shfl_xor_sync(0xFFFFFFFFu, ps, off);
        pd += __shfl_xor_sync(0xFFFFFFFFu, pd, off);
    }
    if (lane == 0) {
        g_es[n] = ps;
        g_ed[n] = pd;
        g_mmax[n] = MMAX_INIT;
        g_ssum[n] = 0.0f;
    }
    g_mu[t]  = mu - LR * er;
    g_agg[t] = 0.0f;
}

// edge pass A: leaky scores + segment max
__global__ void edge_score_kernel(const int* __restrict__ src,
                                  const int* __restrict__ dst) {
    int e = blockIdx.x * blockDim.x + threadIdx.x;
    if (e >= N_EDGES) return;
    int sN = src[e], dN = dst[e];
    float sc = g_es[sN] + g_ed[dN];
    sc = (sc > 0.0f) ? sc : SLOPE * sc;
    g_scores[e] = sc;
    atomicMax(&g_mmax[dN], f_enc(sc));
}

// edge pass B: e = exp(score - max); segment sum
__global__ void edge_exp_kernel(const int* __restrict__ dst) {
    int e = blockIdx.x * blockDim.x + threadIdx.x;
    if (e >= N_EDGES) return;
    int dN = dst[e];
    float m = f_dec(g_mmax[dN]);
    float ev = __expf(0.0f); // placeholder avoided; use expf below
    ev = expf(g_scores[e] - m);
    g_evals[e] = ev;
    atomicAdd(&g_ssum[dN], ev);
}

// edge pass C: alpha = e/(s+1e-8); aggregate alpha*transformed[src] into agg[dst]
// warp per edge, lane = feature. Optionally emit alpha (final step).
__global__ void edge_agg_kernel(const int* __restrict__ src,
                                const int* __restrict__ dst,
                                float* __restrict__ alpha_out,
                                int write_alpha) {
    int t = blockIdx.x * blockDim.x + threadIdx.x;
    int e = t >> 5;
    int lane = t & 31;
    if (e >= N_EDGES) return;
    int sN = src[e], dN = dst[e];
    float alpha = g_evals[e] / (g_ssum[dN] + 1e-8f);
    if (write_alpha && lane == 0) alpha_out[e] = alpha;
    float v = alpha * g_transformed[sN * OUT_F + lane];
    atomicAdd(&g_agg[dN * OUT_F + lane], v);
}

// final: mu_hat = relu(agg); errors = mu - mu_hat; emit mu + errors
__global__ void final_kernel(float* __restrict__ out_mu,
                             float* __restrict__ out_err) {
    int t = blockIdx.x * blockDim.x + threadIdx.x;
    if (t >= N_NODES * OUT_F) return;
    float mh = fmaxf(g_agg[t], 0.0f);
    float mu = g_mu[t];
    out_mu[t]  = mu;
    out_err[t] = mu - mh;
}

// ---------------- launch ----------------
extern "C" void kernel_launch(void* const* d_in, const int* in_sizes, int n_in,
                              void* d_out, int out_size) {
    const float* mu_upper   = (const float*)d_in[0];
    const float* W          = (const float*)d_in[1];
    const float* a_vec      = (const float*)d_in[2];
    const int*   edge_index = (const int*)d_in[3];
    const int*   src = edge_index;
    const int*   dst = edge_index + N_EDGES;

    float* out       = (float*)d_out;
    float* out_mu    = out;
    float* out_err   = out + N_NODES * OUT_F;
    float* out_alpha = out + 2 * N_NODES * OUT_F;

    const int TPB = 256;
    const int nodeThreads = N_NODES * OUT_F;                 // 1.6M
    const int nodeBlocks  = (nodeThreads + TPB - 1) / TPB;
    const int edgeBlocks  = (N_EDGES + TPB - 1) / TPB;
    const int edgeWarpThreads = N_EDGES * 32;                // 25.6M
    const int edgeWarpBlocks  = (edgeWarpThreads + TPB - 1) / TPB;

    init_kernel<<<nodeBlocks, TPB>>>();
    gemm_kernel<<<nodeBlocks, TPB>>>(mu_upper, W);
    deg_kernel<<<edgeBlocks, TPB>>>(dst);
    topdown0_kernel<<<edgeWarpBlocks, TPB>>>(src, dst);

    for (int t = 0; t < N_STEPS; ++t) {
        node_kernel<<<nodeBlocks, TPB>>>(a_vec);
        edge_score_kernel<<<edgeBlocks, TPB>>>(src, dst);
        edge_exp_kernel<<<edgeBlocks, TPB>>>(dst);
        edge_agg_kernel<<<edgeWarpBlocks, TPB>>>(src, dst, out_alpha,
                                                 (t == N_STEPS - 1) ? 1 : 0);
    }
    final_kernel<<<nodeBlocks, TPB>>>(out_mu, out_err);
}

// round 3
// speedup vs baseline: 2.7868x; 2.7868x over previous
#include <cuda_runtime.h>

#define N_NODES 50000
#define N_EDGES 800000
#define IN_F    64
#define OUT_F   32
#define N_STEPS 20
#define LR      0.1f
#define SLOPE   0.2f

// ---------------- scratch (device globals; no allocation allowed) ----------------
__device__ float g_transformed[N_NODES * OUT_F];
__device__ float g_agg[N_NODES * OUT_F];
__device__ float g_mu[N_NODES * OUT_F];
__device__ float g_es[N_NODES];
__device__ float g_ed[N_NODES];
__device__ int   g_degi[N_NODES];
__device__ int   g_rowstart[N_NODES + 1];
__device__ int   g_fill[N_NODES];
__device__ int   g_csr_src[N_EDGES];
__device__ int   g_csr_eid[N_EDGES];

// ---------------- setup kernels ----------------

__global__ void init_kernel() {
    int i = blockIdx.x * blockDim.x + threadIdx.x;
    if (i < N_NODES * OUT_F) g_mu[i] = 0.0f;
    if (i < N_NODES) g_degi[i] = 0;
}

// transformed = mu_upper @ W^T   (N x 64) @ (64 x 32); thread per (node,feature)
__global__ void gemm_kernel(const float* __restrict__ mu_upper,
                            const float* __restrict__ W) {
    __shared__ float Ws[OUT_F * IN_F];
    for (int i = threadIdx.x; i < OUT_F * IN_F; i += blockDim.x)
        Ws[i] = W[i];
    __syncthreads();

    int tid = blockIdx.x * blockDim.x + threadIdx.x;
    if (tid >= N_NODES * OUT_F) return;
    int n = tid >> 5;
    int f = tid & 31;
    const float* row = mu_upper + n * IN_F;
    const float* w   = Ws + f * IN_F;
    float acc = 0.0f;
#pragma unroll
    for (int k = 0; k < IN_F; ++k)
        acc = fmaf(row[k], w[k], acc);
    g_transformed[tid] = acc;
}

__global__ void count_kernel(const int* __restrict__ dst) {
    int e = blockIdx.x * blockDim.x + threadIdx.x;
    if (e >= N_EDGES) return;
    atomicAdd(&g_degi[dst[e]], 1);
}

// single-block exclusive scan over g_degi -> g_rowstart / g_fill
__global__ void scan_kernel() {
    __shared__ int warp_sums[32];
    __shared__ int s_carry;
    int tid  = threadIdx.x;           // 1024 threads
    int lane = tid & 31;
    int wid  = tid >> 5;
    if (tid == 0) s_carry = 0;
    __syncthreads();

    for (int base = 0; base < N_NODES; base += 1024) {
        int idx = base + tid;
        int v = (idx < N_NODES) ? g_degi[idx] : 0;
        // warp inclusive scan
        int x = v;
#pragma unroll
        for (int off = 1; off < 32; off <<= 1) {
            int y = __shfl_up_sync(0xFFFFFFFFu, x, off);
            if (lane >= off) x += y;
        }
        if (lane == 31) warp_sums[wid] = x;
        __syncthreads();
        if (wid == 0) {
            int w = warp_sums[lane];
#pragma unroll
            for (int off = 1; off < 32; off <<= 1) {
                int y = __shfl_up_sync(0xFFFFFFFFu, w, off);
                if (lane >= off) w += y;
            }
            warp_sums[lane] = w;
        }
        __syncthreads();
        int warp_off = (wid > 0) ? warp_sums[wid - 1] : 0;
        int incl = x + warp_off;
        int excl = incl - v;
        if (idx < N_NODES) {
            g_rowstart[idx] = s_carry + excl;
            g_fill[idx]     = s_carry + excl;
        }
        __syncthreads();
        if (tid == 1023) s_carry += incl;   // block total
        __syncthreads();
    }
    if (tid == 0) g_rowstart[N_NODES] = s_carry;
}

__global__ void scatter_kernel(const int* __restrict__ src,
                               const int* __restrict__ dst) {
    int e = blockIdx.x * blockDim.x + threadIdx.x;
    if (e >= N_EDGES) return;
    int pos = atomicAdd(&g_fill[dst[e]], 1);
    g_csr_src[pos] = src[e];
    g_csr_eid[pos] = e;
}

// initial top-down: agg[n] = (1/(deg+1e-8)) * sum_src transformed[src]
// warp per dst node, lane = feature
__global__ void topdown0_kernel() {
    int t = blockIdx.x * blockDim.x + threadIdx.x;
    int n = t >> 5;
    int lane = t & 31;
    if (n >= N_NODES) return;
    int beg = g_rowstart[n], end = g_rowstart[n + 1];
    float acc = 0.0f;
    for (int base = beg; base < end; base += 32) {
        int i = base + lane;
        int s = (i < end) ? g_csr_src[i] : 0;
        int cnt = min(32, end - base);
        for (int j = 0; j < cnt; ++j) {
            int sj = __shfl_sync(0xFFFFFFFFu, s, j);
            acc += g_transformed[sj * OUT_F + lane];
        }
    }
    float inv = 1.0f / ((float)(end - beg) + 1e-8f);
    g_agg[n * OUT_F + lane] = acc * inv;
}

// per step node pass: mu_hat=relu(agg); err=mu-mu_hat; es=err.a_src; ed=err.a_dst; mu-=LR*err
__global__ void node_kernel(const float* __restrict__ a_vec) {
    int t = blockIdx.x * blockDim.x + threadIdx.x;
    int n = t >> 5;
    int lane = t & 31;
    if (n >= N_NODES) return;

    float mh = fmaxf(g_agg[t], 0.0f);
    float mu = g_mu[t];
    float er = mu - mh;

    float ps = er * a_vec[lane];
    float pd = er * a_vec[OUT_F + lane];
#pragma unroll
    for (int off = 16; off > 0; off >>= 1) {
        ps += __shfl_xor_sync(0xFFFFFFFFu, ps, off);
        pd += __shfl_xor_sync(0xFFFFFFFFu, pd, off);
    }
    if (lane == 0) {
        g_es[n] = ps;
        g_ed[n] = pd;
    }
    g_mu[t] = mu - LR * er;
}

// fused per-step edge pass: segment softmax + weighted aggregation, zero atomics.
// warp per dst node, lane = feature (and lane-strided over edges for scalar work)
__global__ void fused_step_kernel(float* __restrict__ alpha_out,
                                  int write_alpha) {
    int t = blockIdx.x * blockDim.x + threadIdx.x;
    int n = t >> 5;
    int lane = t & 31;
    if (n >= N_NODES) return;

    int beg = g_rowstart[n], end = g_rowstart[n + 1];
    float ed_n = g_ed[n];

    // pass 1: segment max (lane-strided)
    float mx = -__int_as_float(0x7F800000);   // -inf
    for (int i = beg + lane; i < end; i += 32) {
        int s = g_csr_src[i];
        float sc = g_es[s] + ed_n;
        sc = (sc > 0.0f) ? sc : SLOPE * sc;
        mx = fmaxf(mx, sc);
    }
#pragma unroll
    for (int off = 16; off > 0; off >>= 1)
        mx = fmaxf(mx, __shfl_xor_sync(0xFFFFFFFFu, mx, off));

    // pass 2: exp + sum + feature accumulation (normalize at the end)
    float sm = 0.0f;
    float acc = 0.0f;
    for (int base = beg; base < end; base += 32) {
        int i = base + lane;
        int s = 0;
        float ev = 0.0f;
        if (i < end) {
            s = g_csr_src[i];
            float sc = g_es[s] + ed_n;
            sc = (sc > 0.0f) ? sc : SLOPE * sc;
            ev = expf(sc - mx);
            sm += ev;
        }
        int cnt = min(32, end - base);
        for (int j = 0; j < cnt; ++j) {
            float evj = __shfl_sync(0xFFFFFFFFu, ev, j);
            int   sj  = __shfl_sync(0xFFFFFFFFu, s, j);
            acc += evj * g_transformed[sj * OUT_F + lane];
        }
    }
#pragma unroll
    for (int off = 16; off > 0; off >>= 1)
        sm += __shfl_xor_sync(0xFFFFFFFFu, sm, off);

    float inv = 1.0f / (sm + 1e-8f);
    g_agg[n * OUT_F + lane] = acc * inv;

    if (write_alpha) {
        for (int i = beg + lane; i < end; i += 32) {
            int s = g_csr_src[i];
            float sc = g_es[s] + ed_n;
            sc = (sc > 0.0f) ? sc : SLOPE * sc;
            alpha_out[g_csr_eid[i]] = expf(sc - mx) * inv;
        }
    }
}

// final: mu_hat = relu(agg); errors = mu - mu_hat; emit mu + errors
__global__ void final_kernel(float* __restrict__ out_mu,
                             float* __restrict__ out_err) {
    int t = blockIdx.x * blockDim.x + threadIdx.x;
    if (t >= N_NODES * OUT_F) return;
    float mh = fmaxf(g_agg[t], 0.0f);
    float mu = g_mu[t];
    out_mu[t]  = mu;
    out_err[t] = mu - mh;
}

// ---------------- launch ----------------
extern "C" void kernel_launch(void* const* d_in, const int* in_sizes, int n_in,
                              void* d_out, int out_size) {
    const float* mu_upper   = (const float*)d_in[0];
    const float* W          = (const float*)d_in[1];
    const float* a_vec      = (const float*)d_in[2];
    const int*   edge_index = (const int*)d_in[3];
    const int*   src = edge_index;
    const int*   dst = edge_index + N_EDGES;

    float* out       = (float*)d_out;
    float* out_mu    = out;
    float* out_err   = out + N_NODES * OUT_F;
    float* out_alpha = out + 2 * N_NODES * OUT_F;

    const int TPB = 256;
    const int nodeThreads = N_NODES * OUT_F;
    const int nodeBlocks  = (nodeThreads + TPB - 1) / TPB;
    const int edgeBlocks  = (N_EDGES + TPB - 1) / TPB;
    const int warpNodeThreads = N_NODES * 32;
    const int warpNodeBlocks  = (warpNodeThreads + TPB - 1) / TPB;

    init_kernel<<<nodeBlocks, TPB>>>();
    gemm_kernel<<<nodeBlocks, TPB>>>(mu_upper, W);
    count_kernel<<<edgeBlocks, TPB>>>(dst);
    scan_kernel<<<1, 1024>>>();
    scatter_kernel<<<edgeBlocks, TPB>>>(src, dst);
    topdown0_kernel<<<warpNodeBlocks, TPB>>>();

    for (int t = 0; t < N_STEPS; ++t) {
        node_kernel<<<warpNodeBlocks, TPB>>>(a_vec);
        fused_step_kernel<<<warpNodeBlocks, TPB>>>(out_alpha,
                                                   (t == N_STEPS - 1) ? 1 : 0);
    }
    final_kernel<<<nodeBlocks, TPB>>>(out_mu, out_err);
}